// round 2
// baseline (speedup 1.0000x reference)
#include <cuda_runtime.h>
#include <cuda_bf16.h>
#include <cstdint>

#define DIN   2048
#define DOUT  2048
#define MTOT  8192

// ---------------- scratch (static device globals; no allocation) ----------------
__device__ int8_t g_xq[(size_t)MTOT * DIN];   // quantized activations, [M][K] int8
__device__ int8_t g_wt[(size_t)DOUT * DIN];   // W transposed+quantized, [N][K] int8

// ---------------- helpers ----------------
__device__ __forceinline__ uint32_t smem_u32(const void* p) {
    uint32_t a;
    asm("{ .reg .u64 t; cvta.to.shared.u64 t, %1; cvt.u32.u64 %0, t; }" : "=r"(a) : "l"(p));
    return a;
}

#define CP_ASYNC16(dst, src) \
    asm volatile("cp.async.cg.shared.global [%0], [%1], 16;" :: "r"(dst), "l"(src) : "memory")
#define CP_ASYNC_COMMIT() asm volatile("cp.async.commit_group;" ::: "memory")
#define CP_ASYNC_WAIT(n)  asm volatile("cp.async.wait_group %0;" :: "n"(n) : "memory")

__device__ __forceinline__ void imma_16832(int* c, uint32_t a0, uint32_t a1, uint32_t a2, uint32_t a3,
                                           uint32_t b0, uint32_t b1) {
    asm volatile(
        "mma.sync.aligned.m16n8k32.row.col.s32.s8.s8.s32 "
        "{%0,%1,%2,%3}, {%4,%5,%6,%7}, {%8,%9}, {%0,%1,%2,%3};"
        : "+r"(c[0]), "+r"(c[1]), "+r"(c[2]), "+r"(c[3])
        : "r"(a0), "r"(a1), "r"(a2), "r"(a3), "r"(b0), "r"(b1));
}

// ---------------- pre-pass 1: quantize x -> int8 ----------------
// Each thread: 16 elements (4x float4 in, 1x int4 out).
__global__ void quant_x_kernel(const float* __restrict__ x, const float* __restrict__ scale_p) {
    const float inv_s = 1.0f / fmaxf(scale_p[0], 1e-8f);
    const int i = blockIdx.x * blockDim.x + threadIdx.x;   // 0 .. M*K/16-1
    const float4* xin = reinterpret_cast<const float4*>(x) + (size_t)i * 4;
    int packed[4];
    #pragma unroll
    for (int j = 0; j < 4; j++) {
        float4 v = xin[j];
        int q0 = __float2int_rn(fminf(fmaxf(v.x * inv_s, -127.f), 127.f));
        int q1 = __float2int_rn(fminf(fmaxf(v.y * inv_s, -127.f), 127.f));
        int q2 = __float2int_rn(fminf(fmaxf(v.z * inv_s, -127.f), 127.f));
        int q3 = __float2int_rn(fminf(fmaxf(v.w * inv_s, -127.f), 127.f));
        packed[j] = (q0 & 0xFF) | ((q1 & 0xFF) << 8) | ((q2 & 0xFF) << 16) | (q3 << 24);
    }
    reinterpret_cast<int4*>(g_xq)[i] = make_int4(packed[0], packed[1], packed[2], packed[3]);
}

// ---------------- pre-pass 2: transpose + quantize W -> int8 [N][K] ----------------
__global__ void conv_wt_kernel(const float* __restrict__ w) {
    __shared__ float t[32][33];
    const int bx = blockIdx.x * 32;   // n tile
    const int by = blockIdx.y * 32;   // k tile
    const int tx = threadIdx.x;       // 0..31
    const int ty = threadIdx.y;       // 0..7
    #pragma unroll
    for (int i = ty; i < 32; i += 8)
        t[by == by ? i : i][tx] = w[(size_t)(by + i) * DOUT + bx + tx];  // t[k][n]
    __syncthreads();
    // write: n = tx, 4 k-values per thread starting at ty*4
    char4 c;
    c.x = (char)__float2int_rn(t[ty * 4 + 0][tx]);
    c.y = (char)__float2int_rn(t[ty * 4 + 1][tx]);
    c.z = (char)__float2int_rn(t[ty * 4 + 2][tx]);
    c.w = (char)__float2int_rn(t[ty * 4 + 3][tx]);
    *reinterpret_cast<char4*>(&g_wt[(size_t)(bx + tx) * DIN + by + ty * 4]) = c;
}

// ---------------- GEMM: out[M,N] = xq @ wt^T + bias (int8 IMMA) ----------------
#define BM 128
#define BN 128
#define BK 64
#define STAGES 4
#define NTHREADS 256
#define NCHUNKS (DIN / BK)        // 32

#define ROW_PITCH 80                       // 64B data + 16B pad -> conflict-free frags
#define A_STAGE   (BM * ROW_PITCH)         // 10240
#define B_STAGE   (BN * ROW_PITCH)         // 10240
#define STAGE_BYTES (A_STAGE + B_STAGE)    // 20480
#define SMEM_TOTAL (STAGES * STAGE_BYTES)  // 81920

__global__ void __launch_bounds__(NTHREADS, 2) gemm_kernel(const float* __restrict__ bias,
                                                           float* __restrict__ out) {
    extern __shared__ __align__(128) char smem[];
    const uint32_t smem_base = smem_u32(smem);

    const int tid  = threadIdx.x;
    const int wid  = tid >> 5;
    const int lane = tid & 31;
    const int wm   = wid >> 2;        // 0..1  (m warp index)
    const int wn   = wid & 3;         // 0..3  (n warp index)
    const int g    = lane >> 2;       // group id (row within frag)
    const int tg   = lane & 3;        // thread-in-group

    const int8_t* Arow = g_xq + (size_t)blockIdx.y * BM * DIN;
    const int8_t* Brow = g_wt + (size_t)blockIdx.x * BN * DIN;

    // per-thread load pattern: 2 A vecs + 2 B vecs of 16B per stage
    const int vec0 = tid;             // 0..255
    const int vec1 = tid + 256;       // 256..511
    const int ra0 = vec0 >> 2, va0 = vec0 & 3;
    const int ra1 = vec1 >> 2, va1 = vec1 & 3;

    auto load_stage = [&](int stage, int chunk) {
        const int k0 = chunk * BK;
        const uint32_t base = smem_base + stage * STAGE_BYTES;
        CP_ASYNC16(base + ra0 * ROW_PITCH + va0 * 16, Arow + (size_t)ra0 * DIN + k0 + va0 * 16);
        CP_ASYNC16(base + ra1 * ROW_PITCH + va1 * 16, Arow + (size_t)ra1 * DIN + k0 + va1 * 16);
        CP_ASYNC16(base + A_STAGE + ra0 * ROW_PITCH + va0 * 16, Brow + (size_t)ra0 * DIN + k0 + va0 * 16);
        CP_ASYNC16(base + A_STAGE + ra1 * ROW_PITCH + va1 * 16, Brow + (size_t)ra1 * DIN + k0 + va1 * 16);
    };

    int acc[4][4][4];
    #pragma unroll
    for (int mi = 0; mi < 4; mi++)
        #pragma unroll
        for (int ni = 0; ni < 4; ni++)
            #pragma unroll
            for (int q = 0; q < 4; q++) acc[mi][ni][q] = 0;

    // prefetch first STAGES-1 chunks
    #pragma unroll
    for (int s = 0; s < STAGES - 1; s++) {
        load_stage(s, s);
        CP_ASYNC_COMMIT();
    }

    const uint32_t aWarpBase = (wm * 64 + g) * ROW_PITCH + tg * 4;
    const uint32_t bWarpBase = (wn * 32 + g) * ROW_PITCH + tg * 4;

    for (int c = 0; c < NCHUNKS; c++) {
        CP_ASYNC_WAIT(STAGES - 2);
        __syncthreads();

        // issue prefetch for chunk c+STAGES-1 into the stage freed at end of iter c-1
        if (c + STAGES - 1 < NCHUNKS) load_stage((c + STAGES - 1) % STAGES, c + STAGES - 1);
        CP_ASYNC_COMMIT();   // unconditional commit keeps wait-group arithmetic uniform

        const uint32_t sA = smem_base + (c % STAGES) * STAGE_BYTES;
        const uint32_t sB = sA + A_STAGE;

        #pragma unroll
        for (int ks = 0; ks < 2; ks++) {
            const uint32_t ko = ks * 32;
            uint32_t b[4][2];
            #pragma unroll
            for (int ni = 0; ni < 4; ni++) {
                uint32_t ad = sB + bWarpBase + ni * 8 * ROW_PITCH + ko;
                asm volatile("ld.shared.u32 %0, [%1];" : "=r"(b[ni][0]) : "r"(ad));
                asm volatile("ld.shared.u32 %0, [%1];" : "=r"(b[ni][1]) : "r"(ad + 16));
            }
            #pragma unroll
            for (int mi = 0; mi < 4; mi++) {
                uint32_t ad = sA + aWarpBase + mi * 16 * ROW_PITCH + ko;
                uint32_t a0, a1, a2, a3;
                asm volatile("ld.shared.u32 %0, [%1];" : "=r"(a0) : "r"(ad));
                asm volatile("ld.shared.u32 %0, [%1];" : "=r"(a1) : "r"(ad + 8 * ROW_PITCH));
                asm volatile("ld.shared.u32 %0, [%1];" : "=r"(a2) : "r"(ad + 16));
                asm volatile("ld.shared.u32 %0, [%1];" : "=r"(a3) : "r"(ad + 8 * ROW_PITCH + 16));
                #pragma unroll
                for (int ni = 0; ni < 4; ni++)
                    imma_16832(acc[mi][ni], a0, a1, a2, a3, b[ni][0], b[ni][1]);
            }
        }
        __syncthreads();
    }
    CP_ASYNC_WAIT(0);

    // -------- epilogue: int32 -> float, + bias, direct coalesced-enough float2 stores --------
    const int gm0 = blockIdx.y * BM + wm * 64;
    const int gn0 = blockIdx.x * BN + wn * 32;
    #pragma unroll
    for (int ni = 0; ni < 4; ni++) {
        const int col = gn0 + ni * 8 + tg * 2;
        const float2 bb = *reinterpret_cast<const float2*>(bias + col);
        #pragma unroll
        for (int mi = 0; mi < 4; mi++) {
            const int row0 = gm0 + mi * 16 + g;
            float2 o0, o1;
            o0.x = __int2float_rn(acc[mi][ni][0]) + bb.x;
            o0.y = __int2float_rn(acc[mi][ni][1]) + bb.y;
            o1.x = __int2float_rn(acc[mi][ni][2]) + bb.x;
            o1.y = __int2float_rn(acc[mi][ni][3]) + bb.y;
            *reinterpret_cast<float2*>(out + (size_t)row0 * DOUT + col)       = o0;
            *reinterpret_cast<float2*>(out + (size_t)(row0 + 8) * DOUT + col) = o1;
        }
    }
}

// ---------------- launch ----------------
extern "C" void kernel_launch(void* const* d_in, const int* in_sizes, int n_in,
                              void* d_out, int out_size) {
    const float* x    = (const float*)d_in[0];   // [4,2048,2048] fp32
    const float* w    = (const float*)d_in[1];   // [2048,2048] fp32
    const float* xs   = (const float*)d_in[2];   // scalar fp32
    const float* bias = (const float*)d_in[3];   // [2048] fp32
    float* out = (float*)d_out;

    quant_x_kernel<<<(MTOT * DIN / 16 + 255) / 256, 256>>>(x, xs);
    conv_wt_kernel<<<dim3(DOUT / 32, DIN / 32), dim3(32, 8)>>>(w);

    static int configured = 0;
    if (!configured) {
        cudaFuncSetAttribute(gemm_kernel, cudaFuncAttributeMaxDynamicSharedMemorySize, SMEM_TOTAL);
        configured = 1;
    }
    gemm_kernel<<<dim3(DOUT / BN, MTOT / BM), NTHREADS, SMEM_TOTAL>>>(bias, out);
}